// round 14
// baseline (speedup 1.0000x reference)
#include <cuda_runtime.h>
#include <cuda_bf16.h>
#include <math.h>

#define B_SZ 512
#define T_SZ 512
#define IN_SZ 128
#define NB 128
#define NT 384
typedef unsigned int u32;
typedef __nv_bfloat16 bf16;

// ---------------- globals (block-swizzled activation storage) ----------------
// blocks: 64 rows x 64 cols bf16 = 8KB, rows 128B, SW128-swizzled inside.
__device__ __align__(16) bf16 g_xh[T_SZ * 2 * 8 * 4096];   // [t][kc2][bg8][4096]
__device__ __align__(16) bf16 g_xl[T_SZ * 2 * 8 * 4096];
__device__ __align__(16) bf16 g_h0h[2][4 * 8 * 4096];      // [buf][kc4][bg8][4096]
__device__ __align__(16) bf16 g_h0l[2][4 * 8 * 4096];
__device__ __align__(16) bf16 g_h1h[2][4 * 8 * 4096];
__device__ __align__(16) bf16 g_h1l[2][4 * 8 * 4096];
__device__ float g_o0[B_SZ * 256], g_o1[B_SZ * 256], g_z[B_SZ * 64];
__device__ unsigned g_gc[8 * 32];
__device__ volatile unsigned g_gp[8 * 32];

__device__ __forceinline__ float sigmoidf_(float x) { return 1.f / (1.f + expf(-x)); }

// ---------------- smem map (bytes) ----------------
#define SM_BIAS 0          // 128 floats
#define SM_DRZ  512        // 64 x 36 f32
#define SM_DN0  9728       // 64 x 20 f32
#define SM_DN1  14848
#define SM_A    20480      // 2 bufs x (hi 8KB | lo 8KB)
#define SM_W    53248      // 178176 B of split weights
#define WO_L0I_H 0
#define WO_L0I_L 13056
#define WO_L0H_H 26112
#define WO_L0H_L 51456
#define WO_L1I_H 76800
#define WO_L1I_L 102144
#define WO_L1H_H 127488
#define WO_L1H_L 152832
#define SMEM_TOTAL 231424

// ---------------- PTX helpers ----------------
__device__ __forceinline__ void ldsm4(u32* r, u32 a) {
    asm volatile("ldmatrix.sync.aligned.m8n8.x4.shared.b16 {%0,%1,%2,%3}, [%4];"
        : "=r"(r[0]), "=r"(r[1]), "=r"(r[2]), "=r"(r[3]) : "r"(a));
}
__device__ __forceinline__ void mma16816(float* d, const u32* a, u32 b0, u32 b1) {
    asm volatile("mma.sync.aligned.m16n8k16.row.col.f32.bf16.bf16.f32 "
        "{%0,%1,%2,%3},{%4,%5,%6,%7},{%8,%9},{%0,%1,%2,%3};"
        : "+f"(d[0]), "+f"(d[1]), "+f"(d[2]), "+f"(d[3])
        : "r"(a[0]), "r"(a[1]), "r"(a[2]), "r"(a[3]), "r"(b0), "r"(b1));
}
#define CPA_COMMIT() asm volatile("cp.async.commit_group;" ::: "memory")
#define CPA_WAIT0()  asm volatile("cp.async.wait_group 0;" ::: "memory")

// Monotonic group barrier over the 16 blocks sharing bg.
__device__ __forceinline__ void group_bar(int bg, unsigned& ph) {
    __syncthreads();
    if (threadIdx.x == 0) {
        __threadfence();
        unsigned p = ph;
        if (atomicAdd(&g_gc[bg * 32], 1u) == p * 16u + 15u) {
            __threadfence();
            g_gp[bg * 32] = p + 1u;
        } else {
            while (g_gp[bg * 32] < p + 1u) { }
            __threadfence();
        }
    }
    __syncthreads();
    ph += 1u;
}

// weight slice (48 rows = 3 gates x 16 units) -> bf16 hi/lo, row-major ld=K+8
__device__ void wsplit(const float* __restrict__ W, int K, int us,
                       char* dh, char* dl, int tid) {
    const int wld = K + 8;
    for (int i = tid; i < 48 * K; i += NT) {
        int n = i / K, k = i % K;
        float w = W[(long)((n >> 4) * 256 + us * 16 + (n & 15)) * K + k];
        bf16 h = __float2bfloat16(w);
        bf16 l = __float2bfloat16(w - __bfloat162float(h));
        ((bf16*)dh)[n * wld + k] = h;
        ((bf16*)dl)[n * wld + k] = l;
    }
}

// ---- cp.async staging: 1024 x 16B units per chunk ([hi 8KB | lo 8KB]) ----
__device__ __forceinline__ void cpa_chunk(u32 dst, const bf16* bh, const bf16* bl, int tid) {
    #pragma unroll
    for (int j = 0; j < 3; j++) {
        int idx = tid + j * NT;
        if (idx < 1024) {
            const bf16* s = (idx & 512) ? bl : bh;
            asm volatile("cp.async.cg.shared.global [%0], [%1], 16;"
                :: "r"(dst + (u32)idx * 16u), "l"(s + (idx & 511) * 8) : "memory");
        }
    }
}

// ---- one 64-K chunk: 4 kt x (4 LDSM.x4 + 6 MMA) ----
__device__ __forceinline__ void compute_chunk(u32 aHi, u32 wH, u32 wL, u32 bOff,
                                              float* a0, float* a1,
                                              int arow128, int axor) {
    #pragma unroll
    for (int kt = 0; kt < 4; kt++) {
        u32 ao = (u32)arow128 + (u32)(axor ^ (kt << 5));
        u32 Ah[4], Al[4], Bh[4], Bl[4];
        ldsm4(Ah, aHi + ao);
        ldsm4(Al, aHi + 8192u + ao);
        u32 bo = bOff + (u32)(kt << 5);
        ldsm4(Bh, wH + bo);
        ldsm4(Bl, wL + bo);
        mma16816(a0, Ah, Bh[0], Bh[2]); mma16816(a1, Ah, Bh[1], Bh[3]);
        mma16816(a0, Ah, Bl[0], Bl[2]); mma16816(a1, Ah, Bl[1], Bl[3]);
        mma16816(a0, Al, Bh[0], Bh[2]); mma16816(a1, Al, Bh[1], Bh[3]);
    }
}

__device__ __forceinline__ void store_acc(float* D, int ld, int cb, int mt, int lane,
                                          const float* a0, const float* a1) {
    int r = mt * 16 + (lane >> 2), c = cb + (lane & 3) * 2;
    *(float2*)&D[r * ld + c]           = make_float2(a0[0], a0[1]);
    *(float2*)&D[(r + 8) * ld + c]     = make_float2(a0[2], a0[3]);
    *(float2*)&D[r * ld + c + 8]       = make_float2(a1[0], a1[1]);
    *(float2*)&D[(r + 8) * ld + c + 8] = make_float2(a1[2], a1[3]);
}

// ---- one layer-stream: n1 ih-chunks + n2 hh-chunks, wait-at-top pipeline ----
// pre: chunk 0's DMA was already issued (cross-step prefetch).
// pxh/pxl: if non-null, issue next-step x chunk-0 DMA at the last chunk and
// L2-warm x chunk 1.
__device__ __forceinline__ void run_stream(
    const bf16* s1h, const bf16* s1l, int n1, u32 w1h, u32 w1l, int wld1,
    const bf16* s2h, const bf16* s2l, int n2, u32 w2h, u32 w2l,
    char* sm, u32 smA, int tid, int lane, int mt, int gate,
    int arow128, int axor, bool pre, const bf16* pxh, const bf16* pxl) {
    const int nch = n1 + n2;
    float a0[4] = {0.f, 0.f, 0.f, 0.f}, a1[4] = {0.f, 0.f, 0.f, 0.f};
    const int brow = gate * 16 + ((lane >> 3) & 1) * 8 + (lane & 7);
    const int bsel = (lane >> 4) * 16;
    const u32 bb1 = (u32)(brow * wld1 * 2 + bsel);
    const u32 bb2 = (u32)(brow * 528 + bsel);
    float* Drz = (float*)(sm + SM_DRZ);
    float* Dn0 = (float*)(sm + SM_DN0);
    float* Dn1 = (float*)(sm + SM_DN1);

    if (!pre) { cpa_chunk(smA, s1h, s1l, tid); CPA_COMMIT(); }
    #pragma unroll 1
    for (int c = 0; c < nch; c++) {
        CPA_WAIT0();         // chunk c's DMA (issued one iteration ago) done
        __syncthreads();     // published; also: all warps done computing c-1
        if (c + 1 < nch) {
            const int cn = c + 1;
            const bf16* bh = (cn < n1) ? s1h + cn * 32768 : s2h + (cn - n1) * 32768;
            const bf16* bl = (cn < n1) ? s1l + cn * 32768 : s2l + (cn - n1) * 32768;
            cpa_chunk(smA + (u32)((cn & 1) * 16384), bh, bl, tid);
            CPA_COMMIT();
        } else if (pxh) {
            // next step's x chunk 0 -> buffer 0 (free: last computed at c=nch-2)
            cpa_chunk(smA, pxh, pxl, tid);
            CPA_COMMIT();
            // L2-warm x chunk 1 (hi: idx<512, lo: idx>=512; 128B lines)
            #pragma unroll
            for (int j = 0; j < 3; j++) {
                int idx = tid + j * NT;
                if (idx < 1024) {
                    const char* p = (idx & 512)
                        ? (const char*)pxl + 65536 + (idx & 511) * 128
                        : (const char*)pxh + 65536 + idx * 128;
                    asm volatile("prefetch.global.L2 [%0];" :: "l"(p));
                }
            }
        }
        const u32 abuf = smA + (u32)((c & 1) * 16384);
        if (c < n1) compute_chunk(abuf, w1h, w1l, bb1 + (u32)(c * 128), a0, a1, arow128, axor);
        else        compute_chunk(abuf, w2h, w2l, bb2 + (u32)((c - n1) * 128), a0, a1, arow128, axor);
        if (gate == 2 && c == n1 - 1) {
            store_acc(Dn0, 20, 0, mt, lane, a0, a1);
            #pragma unroll
            for (int q = 0; q < 4; q++) { a0[q] = 0.f; a1[q] = 0.f; }
        }
    }
    if (gate < 2) store_acc(Drz, 36, gate * 16, mt, lane, a0, a1);
    else          store_acc(Dn1, 20, 0, mt, lane, a0, a1);
}

// ---- epilogue: gate math, h written back as swizzled bf16 hi/lo blocks ----
// No trailing sync: the next stream's head __syncthreads joins stragglers
// before any D-smem rewrite (which sits >=2 loop syncs deeper).
__device__ __forceinline__ void epi_fn(char* sm, int L,
    const bf16* hih, const bf16* hil, bf16* hoh, bf16* hol,
    int us, int tid) {
    __syncthreads();   // D stores visible
    if (tid < 128) {
        const float* Drz = (const float*)(sm + SM_DRZ);
        const float* Dn0 = (const float*)(sm + SM_DN0);
        const float* Dn1 = (const float*)(sm + SM_DN1);
        const float* sb  = (const float*)(sm + SM_BIAS) + L * 64;
        int row = tid >> 1, half = tid & 1;
        int cin = (us & 3) * 16 + half * 8;
        u32 off = (u32)(row * 128 + cin * 2);
        off ^= (off >> 3) & 0x70;
        uint4 hh4 = *(const uint4*)((const char*)hih + off);
        uint4 hl4 = *(const uint4*)((const char*)hil + off);
        const bf16* ph = (const bf16*)&hh4;
        const bf16* pl = (const bf16*)&hl4;
        uint4 oh4, ol4;
        bf16* oh = (bf16*)&oh4;
        bf16* ol = (bf16*)&ol4;
        #pragma unroll
        for (int j = 0; j < 8; j++) {
            int ul = half * 8 + j;
            float rr = sigmoidf_(Drz[row * 36 + ul] + sb[ul]);
            float zz = sigmoidf_(Drz[row * 36 + 16 + ul] + sb[16 + ul]);
            float nn = tanhf(Dn0[row * 20 + ul] + sb[32 + ul]
                             + rr * (Dn1[row * 20 + ul] + sb[48 + ul]));
            float hp = __bfloat162float(ph[j]) + __bfloat162float(pl[j]);
            float h = (1.f - zz) * nn + zz * hp;
            bf16 hb = __float2bfloat16(h);
            oh[j] = hb;
            ol[j] = __float2bfloat16(h - __bfloat162float(hb));
        }
        *(uint4*)((char*)hoh + off) = oh4;
        *(uint4*)((char*)hol + off) = ol4;
    }
}

// one-shot: x -> swizzled bf16 hi/lo blocks  [t][kc][bg][64x64]
__global__ void __launch_bounds__(256) xsplit_kernel(const float* __restrict__ x) {
    for (int q = 0; q < 4; q++) {
        int u = (blockIdx.x * 256 + threadIdx.x) * 4 + q;   // 16B unit id
        int blk = u >> 9, lin = u & 511;
        int row = lin >> 3, c8 = lin & 7;
        int bg = blk & 7, tkc = blk >> 3, kc = tkc & 1, t = tkc >> 1;
        const float* src = x + ((long)(bg * 64 + row) * T_SZ + t) * IN_SZ + kc * 64 + c8 * 8;
        float4 v0 = *(const float4*)src;
        float4 v1 = *(const float4*)(src + 4);
        bf16 h[8], l[8];
        float f[8] = {v0.x, v0.y, v0.z, v0.w, v1.x, v1.y, v1.z, v1.w};
        #pragma unroll
        for (int j = 0; j < 8; j++) {
            h[j] = __float2bfloat16(f[j]);
            l[j] = __float2bfloat16(f[j] - __bfloat162float(h[j]));
        }
        u32 off = (u32)(row * 128 + c8 * 16);
        off ^= (off >> 3) & 0x70;
        *(uint4*)((char*)(g_xh + (long)blk * 4096) + off) = *(uint4*)h;
        *(uint4*)((char*)(g_xl + (long)blk * 4096) + off) = *(uint4*)l;
    }
}

// ---------------- persistent GRU scan ----------------
__global__ void __launch_bounds__(NT) gru_tc(
    const float* __restrict__ W0i, const float* __restrict__ W0h,
    const float* __restrict__ b0i, const float* __restrict__ b0h,
    const float* __restrict__ W1i, const float* __restrict__ W1h,
    const float* __restrict__ b1i, const float* __restrict__ b1h) {
    extern __shared__ char sm[];
    const u32 smb = (u32)__cvta_generic_to_shared(sm);
    const int tid = threadIdx.x;
    const int bg = blockIdx.x >> 4, us = blockIdx.x & 15;
    const int lane = tid & 31, warp = tid >> 5;
    const int mt = warp & 3, gate = warp >> 2;
    const int arow = mt * 16 + (lane & 15);
    const int arow128 = arow * 128;
    const int axor = ((lane >> 4) << 4) ^ ((arow & 7) << 4);
    const u32 smA = smb + SM_A;
    float* sbias = (float*)(sm + SM_BIAS);
    const long eb = (long)((us >> 2) * 8 + bg) * 4096;

    wsplit(W0i, 128, us, sm + SM_W + WO_L0I_H, sm + SM_W + WO_L0I_L, tid);
    wsplit(W0h, 256, us, sm + SM_W + WO_L0H_H, sm + SM_W + WO_L0H_L, tid);
    wsplit(W1i, 256, us, sm + SM_W + WO_L1I_H, sm + SM_W + WO_L1I_L, tid);
    wsplit(W1h, 256, us, sm + SM_W + WO_L1H_H, sm + SM_W + WO_L1H_L, tid);
    if (tid < 128) {
        int L = tid >> 6, part = (tid >> 4) & 3, ul = tid & 15;
        int u = us * 16 + ul;
        const float* bi = L ? b1i : b0i;
        const float* bh = L ? b1h : b0h;
        float val;
        if      (part == 0) val = bi[u] + bh[u];
        else if (part == 1) val = bi[256 + u] + bh[256 + u];
        else if (part == 2) val = bi[512 + u];
        else                val = bh[512 + u];
        sbias[L * 64 + part * 16 + ul] = val;
    }
    // zero initial h (buffer 0): this CTA's 64 rows x 16 cols in all 4 arrays
    if (tid < 128) {
        int row = tid >> 1, half = tid & 1;
        int cin = (us & 3) * 16 + half * 8;
        u32 off = (u32)(row * 128 + cin * 2);
        off ^= (off >> 3) & 0x70;
        uint4 z = make_uint4(0, 0, 0, 0);
        *(uint4*)((char*)(g_h0h[0] + eb) + off) = z;
        *(uint4*)((char*)(g_h0l[0] + eb) + off) = z;
        *(uint4*)((char*)(g_h1h[0] + eb) + off) = z;
        *(uint4*)((char*)(g_h1l[0] + eb) + off) = z;
    }
    unsigned ph = g_gp[bg * 32];
    group_bar(bg, ph);

    for (int t = 0; t < T_SZ; t++) {
        const int r = t & 1, w = r ^ 1;
        const bf16* xh = g_xh + ((long)t * 16 + bg) * 4096;
        const bf16* xl = g_xl + ((long)t * 16 + bg) * 4096;
        run_stream(xh, xl, 2, smb + SM_W + WO_L0I_H, smb + SM_W + WO_L0I_L, 136,
                   g_h0h[r] + bg * 4096, g_h0l[r] + bg * 4096, 4,
                   smb + SM_W + WO_L0H_H, smb + SM_W + WO_L0H_L,
                   sm, smA, tid, lane, mt, gate, arow128, axor,
                   /*pre=*/t > 0, nullptr, nullptr);
        epi_fn(sm, 0, g_h0h[r] + eb, g_h0l[r] + eb, g_h0h[w] + eb, g_h0l[w] + eb, us, tid);
        group_bar(bg, ph);   // peers' h0(t) visible
        const bf16* nxh = (t + 1 < T_SZ) ? g_xh + ((long)(t + 1) * 16 + bg) * 4096 : nullptr;
        const bf16* nxl = (t + 1 < T_SZ) ? g_xl + ((long)(t + 1) * 16 + bg) * 4096 : nullptr;
        run_stream(g_h0h[w] + bg * 4096, g_h0l[w] + bg * 4096, 4,
                   smb + SM_W + WO_L1I_H, smb + SM_W + WO_L1I_L, 264,
                   g_h1h[r] + bg * 4096, g_h1l[r] + bg * 4096, 4,
                   smb + SM_W + WO_L1H_H, smb + SM_W + WO_L1H_L,
                   sm, smA, tid, lane, mt, gate, arow128, axor,
                   /*pre=*/false, nxh, nxl);
        epi_fn(sm, 1, g_h1h[r] + eb, g_h1l[r] + eb, g_h1h[w] + eb, g_h1l[w] + eb, us, tid);
        // no end-of-step sync: next stream's head sync joins epi stragglers
    }
    // final h1 (t=511 odd -> w=0) in buffer 0 (block-swizzled layout)
}

// ---------------- tails ----------------
__global__ void __launch_bounds__(256) lstm_head_kernel(
    const bf16* __restrict__ sh, const bf16* __restrict__ sl, const float* __restrict__ sf,
    const float* __restrict__ Wf, const float* __restrict__ bif, const float* __restrict__ bhf,
    const float* __restrict__ Wr, const float* __restrict__ bir, const float* __restrict__ bhr,
    float* __restrict__ out) {
    __shared__ float ss[256];
    const int b = blockIdx.x, tid = threadIdx.x;
    const int warp = tid >> 5, lane = tid & 31;
    if (sh) {   // h1 in block-swizzled hi/lo layout
        int kc = tid >> 6, bgb = b >> 6;
        long blkb = (long)(kc * 8 + bgb) * 4096 * 2;
        u32 off = (u32)((b & 63) * 128 + (tid & 63) * 2);
        off ^= (off >> 3) & 0x70;
        ss[tid] = __bfloat162float(*(const bf16*)((const char*)sh + blkb + off))
                + __bfloat162float(*(const bf16*)((const char*)sl + blkb + off));
    } else {
        ss[tid] = sf[b * 256 + tid];
    }
    __syncthreads();
    #pragma unroll 1
    for (int oo = 0; oo < 32; oo++) {
        int idx = warp * 32 + oo;
        int hd = idx >> 7, j = idx & 127;
        const float* W = hd ? Wr : Wf;
        const float* bi = hd ? bir : bif;
        const float* bh = hd ? bhr : bhf;
        float di = 0.f, dg = 0.f, doo = 0.f;
        #pragma unroll
        for (int kk = 0; kk < 8; kk++) {
            int k = kk * 32 + lane;
            float sv = ss[k];
            di  += sv * W[(long)j * 256 + k];
            dg  += sv * W[(long)(256 + j) * 256 + k];
            doo += sv * W[(long)(384 + j) * 256 + k];
        }
        #pragma unroll
        for (int off = 16; off; off >>= 1) {
            di  += __shfl_xor_sync(0xffffffffu, di,  off);
            dg  += __shfl_xor_sync(0xffffffffu, dg,  off);
            doo += __shfl_xor_sync(0xffffffffu, doo, off);
        }
        if (lane == 0) {
            di  += bi[j] + bh[j];
            dg  += bi[256 + j] + bh[256 + j];
            doo += bi[384 + j] + bh[384 + j];
            float c = sigmoidf_(di) * tanhf(dg);
            out[b * 256 + hd * 128 + j] = sigmoidf_(doo) * tanhf(c);
        }
    }
}

__device__ __forceinline__ void bspl8(float x, float* bv) {
    const float h = 0.4f;
    float p[12];
    #pragma unroll
    for (int m = 0; m < 12; m++) p[m] = (float)(m - 3) * h - 1.0f;
    float b[11];
    #pragma unroll
    for (int j = 0; j < 11; j++) b[j] = (x >= p[j] && x < p[j + 1]) ? 1.f : 0.f;
    #pragma unroll
    for (int k = 1; k <= 3; k++)
        #pragma unroll
        for (int j = 0; j < 11 - k; j++)
            b[j] = (x - p[j]) / (p[j + k] - p[j]) * b[j]
                 + (p[j + k + 1] - x) / (p[j + k + 1] - p[j + 1]) * b[j + 1];
    #pragma unroll
    for (int j = 0; j < 8; j++) bv[j] = b[j];
}

__global__ void __launch_bounds__(256) kan1_kernel(
    const float* __restrict__ in, const float* __restrict__ base_w,
    const float* __restrict__ spline_w, const float* __restrict__ scaler,
    float* __restrict__ out) {
    __shared__ float silu_s[256];
    __shared__ float bsp_s[256][9];
    const int b = blockIdx.x, tid = threadIdx.x;
    const int warp = tid >> 5, lane = tid & 31;
    {
        float xv = in[b * 256 + tid];
        silu_s[tid] = xv / (1.f + expf(-xv));
        float bv[8]; bspl8(xv, bv);
        #pragma unroll
        for (int k = 0; k < 8; k++) bsp_s[tid][k] = bv[k];
    }
    __syncthreads();
    #pragma unroll 1
    for (int o = warp * 8; o < warp * 8 + 8; o++) {
        float acc = 0.f;
        #pragma unroll
        for (int ii = 0; ii < 8; ii++) {
            int i = ii * 32 + lane;
            acc += silu_s[i] * base_w[o * 256 + i];
            const float4* sp = (const float4*)(spline_w + ((long)o * 256 + i) * 8);
            float4 s0 = sp[0], s1 = sp[1];
            float s8 = bsp_s[i][0] * s0.x + bsp_s[i][1] * s0.y + bsp_s[i][2] * s0.z + bsp_s[i][3] * s0.w
                     + bsp_s[i][4] * s1.x + bsp_s[i][5] * s1.y + bsp_s[i][6] * s1.z + bsp_s[i][7] * s1.w;
            acc += scaler[o * 256 + i] * s8;
        }
        #pragma unroll
        for (int off = 16; off; off >>= 1) acc += __shfl_xor_sync(0xffffffffu, acc, off);
        if (lane == 0) out[b * 64 + o] = acc;
    }
}

__global__ void __launch_bounds__(64) kan2_kernel(
    const float* __restrict__ in, const float* __restrict__ base_w,
    const float* __restrict__ spline_w, const float* __restrict__ scaler,
    float* __restrict__ out) {
    __shared__ float silu_s[64];
    __shared__ float bsp_s[64][9];
    const int b = blockIdx.x, tid = threadIdx.x;
    {
        float xv = in[b * 64 + tid];
        silu_s[tid] = xv / (1.f + expf(-xv));
        float bv[8]; bspl8(xv, bv);
        #pragma unroll
        for (int k = 0; k < 8; k++) bsp_s[tid][k] = bv[k];
    }
    __syncthreads();
    const int warp = tid >> 5, lane = tid & 31;
    if (warp < 2)
        #pragma unroll 1
        for (int o = warp * 5; o < warp * 5 + 5; o++) {
            float acc = 0.f;
            #pragma unroll
            for (int ii = 0; ii < 2; ii++) {
                int i = ii * 32 + lane;
                acc += silu_s[i] * base_w[o * 64 + i];
                const float4* sp = (const float4*)(spline_w + ((long)o * 64 + i) * 8);
                float4 s0 = sp[0], s1 = sp[1];
                float s8 = bsp_s[i][0] * s0.x + bsp_s[i][1] * s0.y + bsp_s[i][2] * s0.z + bsp_s[i][3] * s0.w
                         + bsp_s[i][4] * s1.x + bsp_s[i][5] * s1.y + bsp_s[i][6] * s1.z + bsp_s[i][7] * s1.w;
                acc += scaler[o * 64 + i] * s8;
            }
            #pragma unroll
            for (int off = 16; off; off >>= 1) acc += __shfl_xor_sync(0xffffffffu, acc, off);
            if (lane == 0) out[b * 10 + o] = acc;
        }
}

// ---------------- launch ----------------
extern "C" void kernel_launch(void* const* d_in, const int* in_sizes, int n_in,
                              void* d_out, int out_size) {
    const float* x      = (const float*)d_in[0];
    const float* g0_wih = (const float*)d_in[1];
    const float* g0_whh = (const float*)d_in[2];
    const float* g0_bih = (const float*)d_in[3];
    const float* g0_bhh = (const float*)d_in[4];
    const float* g1_wih = (const float*)d_in[5];
    const float* g1_whh = (const float*)d_in[6];
    const float* g1_bih = (const float*)d_in[7];
    const float* g1_bhh = (const float*)d_in[8];
    const float* lw_ih0  = (const float*)d_in[9];
    const float* lb_ih0  = (const float*)d_in[11];
    const float* lb_hh0  = (const float*)d_in[12];
    const float* lw_ih0r = (const float*)d_in[13];
    const float* lb_ih0r = (const float*)d_in[15];
    const float* lb_hh0r = (const float*)d_in[16];
    const float* lw_ih1  = (const float*)d_in[17];
    const float* lb_ih1  = (const float*)d_in[19];
    const float* lb_hh1  = (const float*)d_in[20];
    const float* lw_ih1r = (const float*)d_in[21];
    const float* lb_ih1r = (const float*)d_in[23];
    const float* lb_hh1r = (const float*)d_in[24];
    const float* kan1_base   = (const float*)d_in[25];
    const float* kan1_spline = (const float*)d_in[26];
    const float* kan1_scaler = (const float*)d_in[27];
    const float* kan2_base   = (const float*)d_in[28];
    const float* kan2_spline = (const float*)d_in[29];
    const float* kan2_scaler = (const float*)d_in[30];

    bf16 *h1h, *h1l; float *o0, *o1, *zz;
    cudaGetSymbolAddress((void**)&h1h, g_h1h);
    cudaGetSymbolAddress((void**)&h1l, g_h1l);
    cudaGetSymbolAddress((void**)&o0, g_o0);
    cudaGetSymbolAddress((void**)&o1, g_o1);
    cudaGetSymbolAddress((void**)&zz, g_z);

    cudaFuncSetAttribute(gru_tc, cudaFuncAttributeMaxDynamicSharedMemorySize, SMEM_TOTAL);

    xsplit_kernel<<<4096, 256>>>(x);
    gru_tc<<<NB, NT, SMEM_TOTAL>>>(g0_wih, g0_whh, g0_bih, g0_bhh,
                                   g1_wih, g1_whh, g1_bih, g1_bhh);
    lstm_head_kernel<<<512, 256>>>(h1h, h1l, nullptr,
                                   lw_ih0, lb_ih0, lb_hh0, lw_ih0r, lb_ih0r, lb_hh0r, o0);
    lstm_head_kernel<<<512, 256>>>(nullptr, nullptr, o0,
                                   lw_ih1, lb_ih1, lb_hh1, lw_ih1r, lb_ih1r, lb_hh1r, o1);
    kan1_kernel<<<512, 256>>>(o1, kan1_base, kan1_spline, kan1_scaler, zz);
    kan2_kernel<<<512, 64>>>(zz, kan2_base, kan2_spline, kan2_scaler, (float*)d_out);
}

// round 15
// speedup vs baseline: 1.0142x; 1.0142x over previous
#include <cuda_runtime.h>
#include <cuda_bf16.h>
#include <math.h>

#define B_SZ 512
#define T_SZ 512
#define IN_SZ 128
#define NB 128
#define NT 384
typedef unsigned int u32;
typedef __nv_bfloat16 bf16;

// ---------------- globals (block-swizzled activation storage) ----------------
__device__ __align__(16) bf16 g_xh[T_SZ * 2 * 8 * 4096];   // [t][kc2][bg8][4096]
__device__ __align__(16) bf16 g_xl[T_SZ * 2 * 8 * 4096];
__device__ __align__(16) bf16 g_h0h[2][4 * 8 * 4096];      // [buf][kc4][bg8][4096]
__device__ __align__(16) bf16 g_h0l[2][4 * 8 * 4096];
__device__ __align__(16) bf16 g_h1h[2][4 * 8 * 4096];
__device__ __align__(16) bf16 g_h1l[2][4 * 8 * 4096];
__device__ float g_o0[B_SZ * 256], g_o1[B_SZ * 256], g_z[B_SZ * 64];
__device__ unsigned g_gc[8 * 32];
__device__ volatile unsigned g_gp[8 * 32];

__device__ __forceinline__ float sigmoidf_(float x) { return 1.f / (1.f + expf(-x)); }

// ---------------- smem map (bytes) ----------------
#define SM_BIAS 0
#define SM_DRZ  512
#define SM_DN0  9728
#define SM_DN1  14848
#define SM_A    20480
#define SM_W    53248
#define WO_L0I_H 0
#define WO_L0I_L 13056
#define WO_L0H_H 26112
#define WO_L0H_L 51456
#define WO_L1I_H 76800
#define WO_L1I_L 102144
#define WO_L1H_H 127488
#define WO_L1H_L 152832
#define SMEM_TOTAL 231424

// ---------------- PTX helpers ----------------
__device__ __forceinline__ void ldsm4(u32* r, u32 a) {
    asm volatile("ldmatrix.sync.aligned.m8n8.x4.shared.b16 {%0,%1,%2,%3}, [%4];"
        : "=r"(r[0]), "=r"(r[1]), "=r"(r[2]), "=r"(r[3]) : "r"(a));
}
__device__ __forceinline__ void mma16816(float* d, const u32* a, u32 b0, u32 b1) {
    asm volatile("mma.sync.aligned.m16n8k16.row.col.f32.bf16.bf16.f32 "
        "{%0,%1,%2,%3},{%4,%5,%6,%7},{%8,%9},{%0,%1,%2,%3};"
        : "+f"(d[0]), "+f"(d[1]), "+f"(d[2]), "+f"(d[3])
        : "r"(a[0]), "r"(a[1]), "r"(a[2]), "r"(a[3]), "r"(b0), "r"(b1));
}
#define CPA_COMMIT() asm volatile("cp.async.commit_group;" ::: "memory")
#define CPA_WAIT0()  asm volatile("cp.async.wait_group 0;" ::: "memory")

// Monotonic group barrier over the 16 blocks sharing bg.
__device__ __forceinline__ void group_bar(int bg, unsigned& ph) {
    __syncthreads();
    if (threadIdx.x == 0) {
        __threadfence();
        unsigned p = ph;
        if (atomicAdd(&g_gc[bg * 32], 1u) == p * 16u + 15u) {
            __threadfence();
            g_gp[bg * 32] = p + 1u;
        } else {
            while (g_gp[bg * 32] < p + 1u) { }
            __threadfence();
        }
    }
    __syncthreads();
    ph += 1u;
}

// weight slice (48 rows = 3 gates x 16 units) -> bf16 hi/lo, row-major ld=K+8
__device__ void wsplit(const float* __restrict__ W, int K, int us,
                       char* dh, char* dl, int tid) {
    const int wld = K + 8;
    for (int i = tid; i < 48 * K; i += NT) {
        int n = i / K, k = i % K;
        float w = W[(long)((n >> 4) * 256 + us * 16 + (n & 15)) * K + k];
        bf16 h = __float2bfloat16(w);
        bf16 l = __float2bfloat16(w - __bfloat162float(h));
        ((bf16*)dh)[n * wld + k] = h;
        ((bf16*)dl)[n * wld + k] = l;
    }
}

// ---- cp.async staging: 1024 x 16B units per chunk ([hi 8KB | lo 8KB]) ----
__device__ __forceinline__ void cpa_chunk(u32 dst, const bf16* bh, const bf16* bl, int tid) {
    #pragma unroll
    for (int j = 0; j < 3; j++) {
        int idx = tid + j * NT;
        if (idx < 1024) {
            const bf16* s = (idx & 512) ? bl : bh;
            asm volatile("cp.async.cg.shared.global [%0], [%1], 16;"
                :: "r"(dst + (u32)idx * 16u), "l"(s + (idx & 511) * 8) : "memory");
        }
    }
}

// ---- one 64-K chunk: 4 kt x (4 LDSM.x4 + 6 MMA) ----
__device__ __forceinline__ void compute_chunk(u32 aHi, u32 wH, u32 wL, u32 bOff,
                                              float* a0, float* a1,
                                              int arow128, int axor) {
    #pragma unroll
    for (int kt = 0; kt < 4; kt++) {
        u32 ao = (u32)arow128 + (u32)(axor ^ (kt << 5));
        u32 Ah[4], Al[4], Bh[4], Bl[4];
        ldsm4(Ah, aHi + ao);
        ldsm4(Al, aHi + 8192u + ao);
        u32 bo = bOff + (u32)(kt << 5);
        ldsm4(Bh, wH + bo);
        ldsm4(Bl, wL + bo);
        mma16816(a0, Ah, Bh[0], Bh[2]); mma16816(a1, Ah, Bh[1], Bh[3]);
        mma16816(a0, Ah, Bl[0], Bl[2]); mma16816(a1, Ah, Bl[1], Bl[3]);
        mma16816(a0, Al, Bh[0], Bh[2]); mma16816(a1, Al, Bh[1], Bh[3]);
    }
}

__device__ __forceinline__ void store_acc(float* D, int ld, int cb, int mt, int lane,
                                          const float* a0, const float* a1) {
    int r = mt * 16 + (lane >> 2), c = cb + (lane & 3) * 2;
    *(float2*)&D[r * ld + c]           = make_float2(a0[0], a0[1]);
    *(float2*)&D[(r + 8) * ld + c]     = make_float2(a0[2], a0[3]);
    *(float2*)&D[r * ld + c + 8]       = make_float2(a1[0], a1[1]);
    *(float2*)&D[(r + 8) * ld + c + 8] = make_float2(a1[2], a1[3]);
}

// ---- one layer-stream: n1 ih-chunks + n2 hh-chunks, cp.async pipelined (R13) ----
__device__ __forceinline__ void run_stream(
    const bf16* s1h, const bf16* s1l, int n1, u32 w1h, u32 w1l, int wld1,
    const bf16* s2h, const bf16* s2l, int n2, u32 w2h, u32 w2l,
    char* sm, u32 smA, int tid, int lane, int mt, int gate,
    int arow128, int axor) {
    const int nch = n1 + n2;
    float a0[4] = {0.f, 0.f, 0.f, 0.f}, a1[4] = {0.f, 0.f, 0.f, 0.f};
    const int brow = gate * 16 + ((lane >> 3) & 1) * 8 + (lane & 7);
    const int bsel = (lane >> 4) * 16;
    const u32 bb1 = (u32)(brow * wld1 * 2 + bsel);
    const u32 bb2 = (u32)(brow * 528 + bsel);
    float* Drz = (float*)(sm + SM_DRZ);
    float* Dn0 = (float*)(sm + SM_DN0);
    float* Dn1 = (float*)(sm + SM_DN1);

    cpa_chunk(smA, s1h, s1l, tid);
    CPA_COMMIT();
    CPA_WAIT0();
    __syncthreads();
    #pragma unroll 1
    for (int c = 0; c < nch; c++) {
        if (c + 1 < nch) {   // issue next-chunk DMA immediately after publish
            const int cn = c + 1;
            const bf16* bh = (cn < n1) ? s1h + cn * 32768 : s2h + (cn - n1) * 32768;
            const bf16* bl = (cn < n1) ? s1l + cn * 32768 : s2l + (cn - n1) * 32768;
            cpa_chunk(smA + (u32)((cn & 1) * 16384), bh, bl, tid);
            CPA_COMMIT();
        }
        const u32 abuf = smA + (u32)((c & 1) * 16384);
        if (c < n1) compute_chunk(abuf, w1h, w1l, bb1 + (u32)(c * 128), a0, a1, arow128, axor);
        else        compute_chunk(abuf, w2h, w2l, bb2 + (u32)((c - n1) * 128), a0, a1, arow128, axor);
        if (gate == 2 && c == n1 - 1) {
            store_acc(Dn0, 20, 0, mt, lane, a0, a1);
            #pragma unroll
            for (int q = 0; q < 4; q++) { a0[q] = 0.f; a1[q] = 0.f; }
        }
        if (c + 1 < nch) CPA_WAIT0();
        __syncthreads();
    }
    if (gate < 2) store_acc(Drz, 36, gate * 16, mt, lane, a0, a1);
    else          store_acc(Dn1, 20, 0, mt, lane, a0, a1);
}

// ---- epilogue: gate math, h written back as swizzled bf16 hi/lo blocks ----
__device__ __forceinline__ void epi_fn(char* sm, int L,
    const bf16* hih, const bf16* hil, bf16* hoh, bf16* hol,
    int us, int tid) {
    __syncthreads();   // D stores visible
    if (tid < 128) {
        const float* Drz = (const float*)(sm + SM_DRZ);
        const float* Dn0 = (const float*)(sm + SM_DN0);
        const float* Dn1 = (const float*)(sm + SM_DN1);
        const float* sb  = (const float*)(sm + SM_BIAS) + L * 64;
        int row = tid >> 1, half = tid & 1;
        int cin = (us & 3) * 16 + half * 8;
        u32 off = (u32)(row * 128 + cin * 2);
        off ^= (off >> 3) & 0x70;
        uint4 hh4 = *(const uint4*)((const char*)hih + off);
        uint4 hl4 = *(const uint4*)((const char*)hil + off);
        const bf16* ph = (const bf16*)&hh4;
        const bf16* pl = (const bf16*)&hl4;
        uint4 oh4, ol4;
        bf16* oh = (bf16*)&oh4;
        bf16* ol = (bf16*)&ol4;
        #pragma unroll
        for (int j = 0; j < 8; j++) {
            int ul = half * 8 + j;
            float rr = sigmoidf_(Drz[row * 36 + ul] + sb[ul]);
            float zz = sigmoidf_(Drz[row * 36 + 16 + ul] + sb[16 + ul]);
            float nn = tanhf(Dn0[row * 20 + ul] + sb[32 + ul]
                             + rr * (Dn1[row * 20 + ul] + sb[48 + ul]));
            float hp = __bfloat162float(ph[j]) + __bfloat162float(pl[j]);
            float h = (1.f - zz) * nn + zz * hp;
            bf16 hb = __float2bfloat16(h);
            oh[j] = hb;
            ol[j] = __float2bfloat16(h - __bfloat162float(hb));
        }
        *(uint4*)((char*)hoh + off) = oh4;
        *(uint4*)((char*)hol + off) = ol4;
    }
}

// one-shot: x -> swizzled bf16 hi/lo blocks  [t][kc][bg][64x64]
__global__ void __launch_bounds__(256) xsplit_kernel(const float* __restrict__ x) {
    for (int q = 0; q < 4; q++) {
        int u = (blockIdx.x * 256 + threadIdx.x) * 4 + q;   // 16B unit id
        int blk = u >> 9, lin = u & 511;
        int row = lin >> 3, c8 = lin & 7;
        int bg = blk & 7, tkc = blk >> 3, kc = tkc & 1, t = tkc >> 1;
        const float* src = x + ((long)(bg * 64 + row) * T_SZ + t) * IN_SZ + kc * 64 + c8 * 8;
        float4 v0 = *(const float4*)src;
        float4 v1 = *(const float4*)(src + 4);
        bf16 h[8], l[8];
        float f[8] = {v0.x, v0.y, v0.z, v0.w, v1.x, v1.y, v1.z, v1.w};
        #pragma unroll
        for (int j = 0; j < 8; j++) {
            h[j] = __float2bfloat16(f[j]);
            l[j] = __float2bfloat16(f[j] - __bfloat162float(h[j]));
        }
        u32 off = (u32)(row * 128 + c8 * 16);
        off ^= (off >> 3) & 0x70;
        *(uint4*)((char*)(g_xh + (long)blk * 4096) + off) = *(uint4*)h;
        *(uint4*)((char*)(g_xl + (long)blk * 4096) + off) = *(uint4*)l;
    }
}

// ---------------- persistent GRU scan (R13 structure) ----------------
__global__ void __launch_bounds__(NT) gru_tc(
    const float* __restrict__ W0i, const float* __restrict__ W0h,
    const float* __restrict__ b0i, const float* __restrict__ b0h,
    const float* __restrict__ W1i, const float* __restrict__ W1h,
    const float* __restrict__ b1i, const float* __restrict__ b1h) {
    extern __shared__ char sm[];
    const u32 smb = (u32)__cvta_generic_to_shared(sm);
    const int tid = threadIdx.x;
    const int bg = blockIdx.x >> 4, us = blockIdx.x & 15;
    const int lane = tid & 31, warp = tid >> 5;
    const int mt = warp & 3, gate = warp >> 2;
    const int arow = mt * 16 + (lane & 15);
    const int arow128 = arow * 128;
    const int axor = ((lane >> 4) << 4) ^ ((arow & 7) << 4);
    const u32 smA = smb + SM_A;
    float* sbias = (float*)(sm + SM_BIAS);
    const long eb = (long)((us >> 2) * 8 + bg) * 4096;

    wsplit(W0i, 128, us, sm + SM_W + WO_L0I_H, sm + SM_W + WO_L0I_L, tid);
    wsplit(W0h, 256, us, sm + SM_W + WO_L0H_H, sm + SM_W + WO_L0H_L, tid);
    wsplit(W1i, 256, us, sm + SM_W + WO_L1I_H, sm + SM_W + WO_L1I_L, tid);
    wsplit(W1h, 256, us, sm + SM_W + WO_L1H_H, sm + SM_W + WO_L1H_L, tid);
    if (tid < 128) {
        int L = tid >> 6, part = (tid >> 4) & 3, ul = tid & 15;
        int u = us * 16 + ul;
        const float* bi = L ? b1i : b0i;
        const float* bh = L ? b1h : b0h;
        float val;
        if      (part == 0) val = bi[u] + bh[u];
        else if (part == 1) val = bi[256 + u] + bh[256 + u];
        else if (part == 2) val = bi[512 + u];
        else                val = bh[512 + u];
        sbias[L * 64 + part * 16 + ul] = val;
    }
    if (tid < 128) {
        int row = tid >> 1, half = tid & 1;
        int cin = (us & 3) * 16 + half * 8;
        u32 off = (u32)(row * 128 + cin * 2);
        off ^= (off >> 3) & 0x70;
        uint4 z = make_uint4(0, 0, 0, 0);
        *(uint4*)((char*)(g_h0h[0] + eb) + off) = z;
        *(uint4*)((char*)(g_h0l[0] + eb) + off) = z;
        *(uint4*)((char*)(g_h1h[0] + eb) + off) = z;
        *(uint4*)((char*)(g_h1l[0] + eb) + off) = z;
    }
    unsigned ph = g_gp[bg * 32];
    group_bar(bg, ph);

    for (int t = 0; t < T_SZ; t++) {
        const int r = t & 1, w = r ^ 1;
        const bf16* xh = g_xh + ((long)t * 16 + bg) * 4096;
        const bf16* xl = g_xl + ((long)t * 16 + bg) * 4096;
        run_stream(xh, xl, 2, smb + SM_W + WO_L0I_H, smb + SM_W + WO_L0I_L, 136,
                   g_h0h[r] + bg * 4096, g_h0l[r] + bg * 4096, 4,
                   smb + SM_W + WO_L0H_H, smb + SM_W + WO_L0H_L,
                   sm, smA, tid, lane, mt, gate, arow128, axor);
        epi_fn(sm, 0, g_h0h[r] + eb, g_h0l[r] + eb, g_h0h[w] + eb, g_h0l[w] + eb, us, tid);
        group_bar(bg, ph);   // peers' h0(t) visible
        run_stream(g_h0h[w] + bg * 4096, g_h0l[w] + bg * 4096, 4,
                   smb + SM_W + WO_L1I_H, smb + SM_W + WO_L1I_L, 264,
                   g_h1h[r] + bg * 4096, g_h1l[r] + bg * 4096, 4,
                   smb + SM_W + WO_L1H_H, smb + SM_W + WO_L1H_L,
                   sm, smA, tid, lane, mt, gate, arow128, axor);
        epi_fn(sm, 1, g_h1h[r] + eb, g_h1l[r] + eb, g_h1h[w] + eb, g_h1l[w] + eb, us, tid);
        __syncthreads();   // h1 epi writes ordered before next step's staging reuse
    }
    // final h1 (t=511 odd -> w=0) in buffer 0 (block-swizzled layout)
}

// ---------- LSTM heads, 4 batch rows per block (amortizes W L2 traffic) ----------
__global__ void __launch_bounds__(256) lstm_head_kernel(
    const bf16* __restrict__ sh, const bf16* __restrict__ sl, const float* __restrict__ sf,
    const float* __restrict__ Wf, const float* __restrict__ bif, const float* __restrict__ bhf,
    const float* __restrict__ Wr, const float* __restrict__ bir, const float* __restrict__ bhr,
    float* __restrict__ out) {
    __shared__ float ss[4][256];
    const int b0 = blockIdx.x * 4, tid = threadIdx.x;
    const int warp = tid >> 5, lane = tid & 31;
    for (int idx = tid; idx < 1024; idx += 256) {
        int rb = idx >> 8, k = idx & 255;
        int b = b0 + rb;
        if (sh) {   // h1 in block-swizzled hi/lo layout
            int kc = k >> 6, bgb = b >> 6;
            long blkb = (long)(kc * 8 + bgb) * 4096 * 2;
            u32 off = (u32)((b & 63) * 128 + (k & 63) * 2);
            off ^= (off >> 3) & 0x70;
            ss[rb][k] = __bfloat162float(*(const bf16*)((const char*)sh + blkb + off))
                      + __bfloat162float(*(const bf16*)((const char*)sl + blkb + off));
        } else {
            ss[rb][k] = sf[b * 256 + k];
        }
    }
    __syncthreads();
    #pragma unroll 1
    for (int oo = 0; oo < 32; oo++) {
        int idx = warp * 32 + oo;
        int hd = idx >> 7, j = idx & 127;
        const float* W = hd ? Wr : Wf;
        const float* bi = hd ? bir : bif;
        const float* bh = hd ? bhr : bhf;
        float di[4] = {0.f, 0.f, 0.f, 0.f};
        float dg[4] = {0.f, 0.f, 0.f, 0.f};
        float doo[4] = {0.f, 0.f, 0.f, 0.f};
        #pragma unroll
        for (int kk = 0; kk < 8; kk++) {
            int k = kk * 32 + lane;
            float wi = W[(long)j * 256 + k];
            float wg = W[(long)(256 + j) * 256 + k];
            float wo = W[(long)(384 + j) * 256 + k];
            #pragma unroll
            for (int rb = 0; rb < 4; rb++) {
                float sv = ss[rb][k];
                di[rb]  += sv * wi;
                dg[rb]  += sv * wg;
                doo[rb] += sv * wo;
            }
        }
        #pragma unroll
        for (int off = 16; off; off >>= 1) {
            #pragma unroll
            for (int rb = 0; rb < 4; rb++) {
                di[rb]  += __shfl_xor_sync(0xffffffffu, di[rb],  off);
                dg[rb]  += __shfl_xor_sync(0xffffffffu, dg[rb],  off);
                doo[rb] += __shfl_xor_sync(0xffffffffu, doo[rb], off);
            }
        }
        if (lane == 0) {
            float b_i = bi[j] + bh[j];
            float b_g = bi[256 + j] + bh[256 + j];
            float b_o = bi[384 + j] + bh[384 + j];
            #pragma unroll
            for (int rb = 0; rb < 4; rb++) {
                float c = sigmoidf_(di[rb] + b_i) * tanhf(dg[rb] + b_g);
                out[(b0 + rb) * 256 + hd * 128 + j] = sigmoidf_(doo[rb] + b_o) * tanhf(c);
            }
        }
    }
}

__device__ __forceinline__ void bspl8(float x, float* bv) {
    const float h = 0.4f;
    float p[12];
    #pragma unroll
    for (int m = 0; m < 12; m++) p[m] = (float)(m - 3) * h - 1.0f;
    float b[11];
    #pragma unroll
    for (int j = 0; j < 11; j++) b[j] = (x >= p[j] && x < p[j + 1]) ? 1.f : 0.f;
    #pragma unroll
    for (int k = 1; k <= 3; k++)
        #pragma unroll
        for (int j = 0; j < 11 - k; j++)
            b[j] = (x - p[j]) / (p[j + k] - p[j]) * b[j]
                 + (p[j + k + 1] - x) / (p[j + k + 1] - p[j + 1]) * b[j + 1];
    #pragma unroll
    for (int j = 0; j < 8; j++) bv[j] = b[j];
}

// kan1, 2 batch rows per block (amortizes spline/base/scaler L2 traffic)
__global__ void __launch_bounds__(256) kan1_kernel(
    const float* __restrict__ in, const float* __restrict__ base_w,
    const float* __restrict__ spline_w, const float* __restrict__ scaler,
    float* __restrict__ out) {
    __shared__ float silu_s[2][256];
    __shared__ float bsp_s[2][256][9];
    const int b0 = blockIdx.x * 2, tid = threadIdx.x;
    const int warp = tid >> 5, lane = tid & 31;
    #pragma unroll
    for (int rb = 0; rb < 2; rb++) {
        float xv = in[(b0 + rb) * 256 + tid];
        silu_s[rb][tid] = xv / (1.f + expf(-xv));
        float bv[8]; bspl8(xv, bv);
        #pragma unroll
        for (int k = 0; k < 8; k++) bsp_s[rb][tid][k] = bv[k];
    }
    __syncthreads();
    #pragma unroll 1
    for (int o = warp * 8; o < warp * 8 + 8; o++) {
        float acc0 = 0.f, acc1 = 0.f;
        #pragma unroll
        for (int ii = 0; ii < 8; ii++) {
            int i = ii * 32 + lane;
            float bw = base_w[o * 256 + i];
            float sc = scaler[o * 256 + i];
            const float4* sp = (const float4*)(spline_w + ((long)o * 256 + i) * 8);
            float4 s0 = sp[0], s1 = sp[1];
            {
                const float* bs = &bsp_s[0][i][0];
                float s8 = bs[0]*s0.x + bs[1]*s0.y + bs[2]*s0.z + bs[3]*s0.w
                         + bs[4]*s1.x + bs[5]*s1.y + bs[6]*s1.z + bs[7]*s1.w;
                acc0 += silu_s[0][i] * bw + sc * s8;
            }
            {
                const float* bs = &bsp_s[1][i][0];
                float s8 = bs[0]*s0.x + bs[1]*s0.y + bs[2]*s0.z + bs[3]*s0.w
                         + bs[4]*s1.x + bs[5]*s1.y + bs[6]*s1.z + bs[7]*s1.w;
                acc1 += silu_s[1][i] * bw + sc * s8;
            }
        }
        #pragma unroll
        for (int off = 16; off; off >>= 1) {
            acc0 += __shfl_xor_sync(0xffffffffu, acc0, off);
            acc1 += __shfl_xor_sync(0xffffffffu, acc1, off);
        }
        if (lane == 0) {
            out[b0 * 64 + o] = acc0;
            out[(b0 + 1) * 64 + o] = acc1;
        }
    }
}

__global__ void __launch_bounds__(64) kan2_kernel(
    const float* __restrict__ in, const float* __restrict__ base_w,
    const float* __restrict__ spline_w, const float* __restrict__ scaler,
    float* __restrict__ out) {
    __shared__ float silu_s[64];
    __shared__ float bsp_s[64][9];
    const int b = blockIdx.x, tid = threadIdx.x;
    {
        float xv = in[b * 64 + tid];
        silu_s[tid] = xv / (1.f + expf(-xv));
        float bv[8]; bspl8(xv, bv);
        #pragma unroll
        for (int k = 0; k < 8; k++) bsp_s[tid][k] = bv[k];
    }
    __syncthreads();
    const int warp = tid >> 5, lane = tid & 31;
    if (warp < 2)
        #pragma unroll 1
        for (int o = warp * 5; o < warp * 5 + 5; o++) {
            float acc = 0.f;
            #pragma unroll
            for (int ii = 0; ii < 2; ii++) {
                int i = ii * 32 + lane;
                acc += silu_s[i] * base_w[o * 64 + i];
                const float4* sp = (const float4*)(spline_w + ((long)o * 64 + i) * 8);
                float4 s0 = sp[0], s1 = sp[1];
                float s8 = bsp_s[i][0]*s0.x + bsp_s[i][1]*s0.y + bsp_s[i][2]*s0.z + bsp_s[i][3]*s0.w
                         + bsp_s[i][4]*s1.x + bsp_s[i][5]*s1.y + bsp_s[i][6]*s1.z + bsp_s[i][7]*s1.w;
                acc += scaler[o * 64 + i] * s8;
            }
            #pragma unroll
            for (int off = 16; off; off >>= 1) acc += __shfl_xor_sync(0xffffffffu, acc, off);
            if (lane == 0) out[b * 10 + o] = acc;
        }
}

// ---------------- launch ----------------
extern "C" void kernel_launch(void* const* d_in, const int* in_sizes, int n_in,
                              void* d_out, int out_size) {
    const float* x      = (const float*)d_in[0];
    const float* g0_wih = (const float*)d_in[1];
    const float* g0_whh = (const float*)d_in[2];
    const float* g0_bih = (const float*)d_in[3];
    const float* g0_bhh = (const float*)d_in[4];
    const float* g1_wih = (const float*)d_in[5];
    const float* g1_whh = (const float*)d_in[6];
    const float* g1_bih = (const float*)d_in[7];
    const float* g1_bhh = (const float*)d_in[8];
    const float* lw_ih0  = (const float*)d_in[9];
    const float* lb_ih0  = (const float*)d_in[11];
    const float* lb_hh0  = (const float*)d_in[12];
    const float* lw_ih0r = (const float*)d_in[13];
    const float* lb_ih0r = (const float*)d_in[15];
    const float* lb_hh0r = (const float*)d_in[16];
    const float* lw_ih1  = (const float*)d_in[17];
    const float* lb_ih1  = (const float*)d_in[19];
    const float* lb_hh1  = (const float*)d_in[20];
    const float* lw_ih1r = (const float*)d_in[21];
    const float* lb_ih1r = (const float*)d_in[23];
    const float* lb_hh1r = (const float*)d_in[24];
    const float* kan1_base   = (const float*)d_in[25];
    const float* kan1_spline = (const float*)d_in[26];
    const float* kan1_scaler = (const float*)d_in[27];
    const float* kan2_base   = (const float*)d_in[28];
    const float* kan2_spline = (const float*)d_in[29];
    const float* kan2_scaler = (const float*)d_in[30];

    bf16 *h1h, *h1l; float *o0, *o1, *zz;
    cudaGetSymbolAddress((void**)&h1h, g_h1h);
    cudaGetSymbolAddress((void**)&h1l, g_h1l);
    cudaGetSymbolAddress((void**)&o0, g_o0);
    cudaGetSymbolAddress((void**)&o1, g_o1);
    cudaGetSymbolAddress((void**)&zz, g_z);

    cudaFuncSetAttribute(gru_tc, cudaFuncAttributeMaxDynamicSharedMemorySize, SMEM_TOTAL);

    xsplit_kernel<<<4096, 256>>>(x);
    gru_tc<<<NB, NT, SMEM_TOTAL>>>(g0_wih, g0_whh, g0_bih, g0_bhh,
                                   g1_wih, g1_whh, g1_bih, g1_bhh);
    lstm_head_kernel<<<128, 256>>>(h1h, h1l, nullptr,
                                   lw_ih0, lb_ih0, lb_hh0, lw_ih0r, lb_ih0r, lb_hh0r, o0);
    lstm_head_kernel<<<128, 256>>>(nullptr, nullptr, o0,
                                   lw_ih1, lb_ih1, lb_hh1, lw_ih1r, lb_ih1r, lb_hh1r, o1);
    kan1_kernel<<<256, 256>>>(o1, kan1_base, kan1_spline, kan1_scaler, zz);
    kan2_kernel<<<512, 64>>>(zz, kan2_base, kan2_spline, kan2_scaler, (float*)d_out);
}